// round 5
// baseline (speedup 1.0000x reference)
#include <cuda_runtime.h>
#include <cstdint>
#include <cstddef>

#define B_  32
#define T_  2048
#define D_  512
#define L_  512
#define NG  2048          // 3L gate cols + L candidate cols
#define GW  1536          // w_w column count

// 536 MB scratch for precomputed x-part of preactivations (+bias folded in).
// Layout: g_pre[(b*T + t)*NG + col]
__device__ float g_pre[(size_t)B_ * T_ * NG];
__device__ unsigned int g_bar;

// Packed dual-fp32 FMA (Blackwell f32x2 pipe: 2 FMAs per issue slot).
#define FMA_F32X2(d, a, b, c) \
    asm("fma.rn.f32x2 %0, %1, %2, %3;" : "=l"(d) : "l"(a), "l"(b), "l"(c))

__device__ __forceinline__ float2 unpack_f32x2(unsigned long long v) {
    float2 r;
    asm("mov.b64 {%0, %1}, %2;" : "=f"(r.x), "=f"(r.y) : "l"(v));
    return r;
}

// ---------------------------------------------------------------------------
// Phase 1: PRE = X @ W_x + bias     (X: [65536, 512], W_x: [512, 2048])
// f32x2 packed FMAs; B tile stored DUPLICATED so (w,w) pairs load directly.
// Also resets the grid-barrier counter (stream-ordered before lstm_kernel).
// ---------------------------------------------------------------------------
__global__ __launch_bounds__(256, 3)
void gemm_pre_kernel(const float* __restrict__ X,
                     const float* __restrict__ ww, const float* __restrict__ wb,
                     const float* __restrict__ mw, const float* __restrict__ mb)
{
    __shared__ float As[16][132];    // A tile, transposed: As[k][m]
    __shared__ float Bsd[16][136];   // B tile, duplicated: col n at 2n, 2n+1

    if (blockIdx.x == 0 && blockIdx.y == 0 && threadIdx.x == 0) g_bar = 0u;

    const int n0 = blockIdx.x * 64;
    const int m0 = blockIdx.y * 128;
    const int tid = threadIdx.x;
    const int tx = tid & 15;        // n direction (16 * 4 = 64)
    const int ty = tid >> 4;        // m direction (16 * 8 = 128)

    const float* Bp; int ldb; const float* bias;
    if (n0 < GW) { Bp = ww + n0;        ldb = GW; bias = wb + n0; }
    else         { Bp = mw + (n0 - GW); ldb = L_; bias = mb + (n0 - GW); }

    unsigned long long accp[4][4];   // pair p = rows (ty*8+2p, +1), col tx*4+j
    #pragma unroll
    for (int p = 0; p < 4; p++)
        #pragma unroll
        for (int j = 0; j < 4; j++) accp[p][j] = 0ull;

    const int arow = tid >> 2;          // 0..63
    const int ak   = (tid & 3) * 4;     // 0,4,8,12
    const int brow = tid >> 4;          // 0..15
    const int bc   = (tid & 15) * 4;    // 0..60

    for (int k0 = 0; k0 < D_; k0 += 16) {
        #pragma unroll
        for (int h = 0; h < 2; h++) {
            int row = arow + h * 64;
            float4 v = *(const float4*)&X[(size_t)(m0 + row) * D_ + k0 + ak];
            As[ak + 0][row] = v.x; As[ak + 1][row] = v.y;
            As[ak + 2][row] = v.z; As[ak + 3][row] = v.w;
        }
        {
            float4 v = *(const float4*)&Bp[(size_t)(k0 + brow) * ldb + bc];
            float4 d0 = make_float4(v.x, v.x, v.y, v.y);
            float4 d1 = make_float4(v.z, v.z, v.w, v.w);
            *(float4*)&Bsd[brow][bc * 2]     = d0;
            *(float4*)&Bsd[brow][bc * 2 + 4] = d1;
        }
        __syncthreads();

        #pragma unroll
        for (int kk = 0; kk < 16; kk++) {
            const ulonglong2* apv = (const ulonglong2*)&As[kk][ty * 8];
            ulonglong2 a01 = apv[0];
            ulonglong2 a23 = apv[1];
            const ulonglong2* bpv = (const ulonglong2*)&Bsd[kk][tx * 8];
            ulonglong2 b01 = bpv[0];
            ulonglong2 b23 = bpv[1];
            unsigned long long ap[4] = {a01.x, a01.y, a23.x, a23.y};
            unsigned long long bp[4] = {b01.x, b01.y, b23.x, b23.y};
            #pragma unroll
            for (int p = 0; p < 4; p++)
                #pragma unroll
                for (int j = 0; j < 4; j++)
                    FMA_F32X2(accp[p][j], ap[p], bp[j], accp[p][j]);
        }
        __syncthreads();
    }

    float4 bias4 = *(const float4*)&bias[tx * 4];
    float bj[4] = {bias4.x, bias4.y, bias4.z, bias4.w};
    #pragma unroll
    for (int p = 0; p < 4; p++) {
        float2 f[4];
        #pragma unroll
        for (int j = 0; j < 4; j++) f[j] = unpack_f32x2(accp[p][j]);
        int r0 = m0 + ty * 8 + 2 * p;
        float4 o0, o1;
        o0.x = f[0].x + bj[0]; o0.y = f[1].x + bj[1];
        o0.z = f[2].x + bj[2]; o0.w = f[3].x + bj[3];
        o1.x = f[0].y + bj[0]; o1.y = f[1].y + bj[1];
        o1.z = f[2].y + bj[2]; o1.w = f[3].y + bj[3];
        *(float4*)&g_pre[(size_t)r0 * NG + n0 + tx * 4]       = o0;
        *(float4*)&g_pre[(size_t)(r0 + 1) * NG + n0 + tx * 4] = o1;
    }
}

// ---------------------------------------------------------------------------
// Phase 2: persistent recurrent kernel (f32x2 GEMM inner loop).
// 128 CTAs, CTA bx owns l in [bx*4, bx*4+4) => 16 gate columns.
// W_h slice cached DUPLICATED in smem; c in registers; h round-trips through
// the output buffer; grid sync via monotonic counter (reset by gemm kernel).
// ---------------------------------------------------------------------------
#define NCTA 128
#define NTHR 256
// smem: sH[512][36] (h, k-major) + sWd[512][36] (dup Wh cols) + sRed[256][20]
#define SMEM_FLOATS (512*36 + 512*36 + 256*20)

__device__ __forceinline__ float sigf(float x)     { return 1.f / (1.f + __expf(-x)); }
__device__ __forceinline__ float tanh_fast(float x){ return 2.f / (1.f + __expf(-2.f * x)) - 1.f; }

__global__ __launch_bounds__(NTHR, 1)
void lstm_kernel(const float* __restrict__ h0, const float* __restrict__ c0,
                 const float* __restrict__ ww, const float* __restrict__ mw,
                 float* __restrict__ out)
{
    extern __shared__ float smem[];
    float* sH   = smem;                 // sH[k*36 + b]
    float* sWd  = smem + 512 * 36;      // sWd[k*36 + 2j + {0,1}] (duplicated)
    float* sRed = sWd + 512 * 36;       // sRed[tid*20 + v]

    const int tid = threadIdx.x;
    const int L0  = blockIdx.x * 4;

    // ---- load W_h slice once (duplicated): col(j) = (j>>2)*512 + L0 + (j&3) ----
    for (int it = tid; it < 16 * 512; it += NTHR) {
        int k = it >> 4;
        int j = it & 15;
        int g = j >> 2, jl = j & 3;
        float w;
        if (g < 3) w = ww[(size_t)(512 + k) * GW + g * 512 + L0 + jl];
        else       w = mw[(size_t)(512 + k) * L_ + L0 + jl];
        sWd[k * 36 + 2 * j]     = w;
        sWd[k * 36 + 2 * j + 1] = w;
    }

    // dot-product mapping: 8-way K split (warp = K chunk), 4x4 register block
    const int s  = tid >> 5;            // K chunk 0..7 (k in [s*64, s*64+64))
    const int u  = tid & 31;
    const int b0 = (u >> 2) * 4;        // batch block
    const int j0 = (u & 3) * 4;         // column block
    const int kbase = s * 64;

    // epilogue mapping (tid < 128): one (b, l) pair per thread
    const int eb  = tid >> 2;
    const int ejl = tid & 3;
    float c_reg = 0.f;
    float pre_r[4];
    if (tid < 128) {
        c_reg = c0[eb * L_ + L0 + ejl];
        #pragma unroll
        for (int g = 0; g < 4; g++)
            pre_r[g] = g_pre[(size_t)eb * T_ * NG + g * 512 + L0 + ejl];
    }

    // initial sH from h0 [32][512]
    #pragma unroll
    for (int q = 0; q < 16; q++) {
        int fidx = q * 256 + tid;
        int b = fidx >> 7;
        int kf = fidx & 127;
        float4 v = *(const float4*)&h0[b * 512 + kf * 4];
        int kb = kf * 4;
        sH[(kb + 0) * 36 + b] = v.x;
        sH[(kb + 1) * 36 + b] = v.y;
        sH[(kb + 2) * 36 + b] = v.z;
        sH[(kb + 3) * 36 + b] = v.w;
    }

    float* hid  = out;
    float* cell = out + (size_t)B_ * T_ * L_;

    for (int t = 0; t < T_; t++) {
        __syncthreads();    // sH (and on t==0: sWd) ready

        // ---- h-part dot product: f32x2 packed, pairs over batch ----
        unsigned long long accp[2][4];   // pair p = batches (b0+2p, +1), col j0+j
        #pragma unroll
        for (int p = 0; p < 2; p++)
            #pragma unroll
            for (int j = 0; j < 4; j++) accp[p][j] = 0ull;

        const float* hp = sH  + kbase * 36 + b0;
        const float* wp = sWd + kbase * 36 + j0 * 2;
        #pragma unroll 8
        for (int kk = 0; kk < 64; kk++) {
            ulonglong2 h2  = *(const ulonglong2*)hp;         // (b0,b0+1),(b0+2,b0+3)
            ulonglong2 w01 = *(const ulonglong2*)wp;         // (wj0,wj0),(wj1,wj1)
            ulonglong2 w23 = *(const ulonglong2*)(wp + 4);   // (wj2,wj2),(wj3,wj3)
            unsigned long long hpair[2] = {h2.x, h2.y};
            unsigned long long wpair[4] = {w01.x, w01.y, w23.x, w23.y};
            #pragma unroll
            for (int p = 0; p < 2; p++)
                #pragma unroll
                for (int j = 0; j < 4; j++)
                    FMA_F32X2(accp[p][j], hpair[p], wpair[j], accp[p][j]);
            hp += 36; wp += 36;
        }
        #pragma unroll
        for (int p = 0; p < 2; p++)
            #pragma unroll
            for (int j = 0; j < 4; j++) {
                float2 f = unpack_f32x2(accp[p][j]);
                sRed[tid * 20 + (2 * p) * 4 + j]     = f.x;
                sRed[tid * 20 + (2 * p + 1) * 4 + j] = f.y;
            }
        __syncthreads();

        // ---- reduce K chunks + gate epilogue ----
        if (tid < 128) {
            float z[4];
            #pragma unroll
            for (int g = 0; g < 4; g++) {
                float v = 0.f;
                #pragma unroll
                for (int ss = 0; ss < 8; ss++)
                    v += sRed[(ss * 32 + (eb >> 2) * 4 + g) * 20 + (eb & 3) * 4 + ejl];
                z[g] = v + pre_r[g];
            }
            float ig = sigf(z[0]);
            float fg = sigf(z[1]);
            float og = sigf(z[2]);
            float mg = tanh_fast(z[3]);
            c_reg = fg * c_reg + ig * mg;
            float hn = og * tanh_fast(c_reg);
            size_t off = ((size_t)eb * T_ + t) * L_ + L0 + ejl;
            hid[off]  = hn;
            cell[off] = c_reg;
            if (t + 1 < T_) {   // prefetch next step's x-part early
                #pragma unroll
                for (int g = 0; g < 4; g++)
                    pre_r[g] = g_pre[((size_t)eb * T_ + (t + 1)) * NG + g * 512 + L0 + ejl];
            }
        }

        if (t + 1 < T_) {
            // ---- grid barrier (monotonic counter, reset per launch by gemm) ----
            __threadfence();
            __syncthreads();
            if (tid == 0) {
                atomicAdd(&g_bar, 1u);
                unsigned target = (unsigned)(t + 1) * NCTA;
                while (*(volatile unsigned*)&g_bar < target) { }
                __threadfence();
            }
            __syncthreads();
            // ---- stage h(t) for next step ----
            #pragma unroll
            for (int q = 0; q < 16; q++) {
                int fidx = q * 256 + tid;
                int b = fidx >> 7;
                int kf = fidx & 127;
                float4 v = *(const float4*)&hid[((size_t)b * T_ + t) * L_ + kf * 4];
                int kb = kf * 4;
                sH[(kb + 0) * 36 + b] = v.x;
                sH[(kb + 1) * 36 + b] = v.y;
                sH[(kb + 2) * 36 + b] = v.z;
                sH[(kb + 3) * 36 + b] = v.w;
            }
        }
    }
}

// ---------------------------------------------------------------------------
extern "C" void kernel_launch(void* const* d_in, const int* in_sizes, int n_in,
                              void* d_out, int out_size)
{
    const float* x  = (const float*)d_in[0];
    const float* h0 = (const float*)d_in[1];
    const float* c0 = (const float*)d_in[2];
    const float* ww = (const float*)d_in[3];
    const float* wb = (const float*)d_in[4];
    const float* mw = (const float*)d_in[5];
    const float* mb = (const float*)d_in[6];
    float* out = (float*)d_out;

    cudaFuncSetAttribute(lstm_kernel,
                         cudaFuncAttributeMaxDynamicSharedMemorySize,
                         SMEM_FLOATS * (int)sizeof(float));

    gemm_pre_kernel<<<dim3(NG / 64, (B_ * T_) / 128), 256>>>(x, ww, wb, mw, mb);
    lstm_kernel<<<NCTA, NTHR, SMEM_FLOATS * (int)sizeof(float)>>>(h0, c0, ww, mw, out);
}

// round 6
// speedup vs baseline: 1.1192x; 1.1192x over previous
#include <cuda_runtime.h>
#include <cstdint>
#include <cstddef>

#define B_  32
#define T_  2048
#define D_  512
#define L_  512
#define NG  2048          // 3L gate cols + L candidate cols
#define GW  1536          // w_w column count

// 536 MB scratch for precomputed x-part of preactivations (+bias folded in).
// Layout: g_pre[(b*T + t)*NG + col]
__device__ float g_pre[(size_t)B_ * T_ * NG];

#define NCTA 128
// Per-CTA step flags, 32B stride (one L2 sector each). No atomics.
__device__ unsigned int g_flags[NCTA * 8];

__device__ __forceinline__ unsigned ld_acq(const unsigned* p) {
    unsigned v;
    asm volatile("ld.acquire.gpu.global.u32 %0, [%1];" : "=r"(v) : "l"(p));
    return v;
}
__device__ __forceinline__ void st_rel(unsigned* p, unsigned v) {
    asm volatile("st.release.gpu.global.u32 [%0], %1;" :: "l"(p), "r"(v));
}

// ---------------------------------------------------------------------------
// Phase 1: PRE = X @ W_x + bias     (X: [65536, 512], W_x: [512, 2048])
// 128x128 tile, 8x8 microtile, 2 CTAs/SM. Also resets the step flags
// (stream-ordered before lstm_kernel).
// ---------------------------------------------------------------------------
__global__ __launch_bounds__(256, 2)
void gemm_pre_kernel(const float* __restrict__ X,
                     const float* __restrict__ ww, const float* __restrict__ wb,
                     const float* __restrict__ mw, const float* __restrict__ mb)
{
    __shared__ float As[16][132];   // A tile, transposed: As[k][m], m=0..127
    __shared__ float Bs[16][136];   // B tile: Bs[k][n], n=0..127

    const int tid = threadIdx.x;
    if (blockIdx.x == 0 && blockIdx.y == 0) {
        #pragma unroll
        for (int r = 0; r < 4; r++) g_flags[tid * 4 + r] = 0u;
    }

    const int n0 = blockIdx.x * 128;
    const int m0 = blockIdx.y * 128;
    const int tx = tid & 15;        // n direction (16 * 8 = 128)
    const int ty = tid >> 4;        // m direction (16 * 8 = 128)

    const float* Bp; int ldb; const float* bias;
    if (n0 < GW) { Bp = ww + n0;        ldb = GW; bias = wb + n0; }
    else         { Bp = mw + (n0 - GW); ldb = L_; bias = mb + (n0 - GW); }

    float acc[8][8];
    #pragma unroll
    for (int i = 0; i < 8; i++)
        #pragma unroll
        for (int j = 0; j < 8; j++) acc[i][j] = 0.f;

    const int arow = tid >> 1;          // 0..127
    const int ak   = (tid & 1) * 8;     // 0 or 8
    const int brow = tid >> 4;          // 0..15
    const int bc   = (tid & 15) * 8;    // 0..120

    for (int k0 = 0; k0 < D_; k0 += 16) {
        {
            float4 v0 = *(const float4*)&X[(size_t)(m0 + arow) * D_ + k0 + ak];
            float4 v1 = *(const float4*)&X[(size_t)(m0 + arow) * D_ + k0 + ak + 4];
            As[ak + 0][arow] = v0.x; As[ak + 1][arow] = v0.y;
            As[ak + 2][arow] = v0.z; As[ak + 3][arow] = v0.w;
            As[ak + 4][arow] = v1.x; As[ak + 5][arow] = v1.y;
            As[ak + 6][arow] = v1.z; As[ak + 7][arow] = v1.w;
        }
        {
            float4 v0 = *(const float4*)&Bp[(size_t)(k0 + brow) * ldb + bc];
            float4 v1 = *(const float4*)&Bp[(size_t)(k0 + brow) * ldb + bc + 4];
            *(float4*)&Bs[brow][bc]     = v0;
            *(float4*)&Bs[brow][bc + 4] = v1;
        }
        __syncthreads();

        #pragma unroll
        for (int kk = 0; kk < 16; kk++) {
            float a[8], b[8];
            *(float4*)(a)     = *(const float4*)&As[kk][ty * 8];
            *(float4*)(a + 4) = *(const float4*)&As[kk][ty * 8 + 4];
            *(float4*)(b)     = *(const float4*)&Bs[kk][tx * 8];
            *(float4*)(b + 4) = *(const float4*)&Bs[kk][tx * 8 + 4];
            #pragma unroll
            for (int i = 0; i < 8; i++)
                #pragma unroll
                for (int j = 0; j < 8; j++)
                    acc[i][j] += a[i] * b[j];
        }
        __syncthreads();
    }

    float bj[8];
    *(float4*)(bj)     = *(const float4*)&bias[tx * 8];
    *(float4*)(bj + 4) = *(const float4*)&bias[tx * 8 + 4];
    #pragma unroll
    for (int i = 0; i < 8; i++) {
        int r = m0 + ty * 8 + i;
        float4 o0, o1;
        o0.x = acc[i][0] + bj[0]; o0.y = acc[i][1] + bj[1];
        o0.z = acc[i][2] + bj[2]; o0.w = acc[i][3] + bj[3];
        o1.x = acc[i][4] + bj[4]; o1.y = acc[i][5] + bj[5];
        o1.z = acc[i][6] + bj[6]; o1.w = acc[i][7] + bj[7];
        *(float4*)&g_pre[(size_t)r * NG + n0 + tx * 8]     = o0;
        *(float4*)&g_pre[(size_t)r * NG + n0 + tx * 8 + 4] = o1;
    }
}

// ---------------------------------------------------------------------------
// Phase 2: persistent recurrent kernel (scalar FFMA inner loop, round-4 form).
// 128 CTAs, CTA bx owns l in [bx*4, bx*4+4) => 16 gate columns.
// W_h slice cached in smem; c in registers; h round-trips through the output
// buffer. Grid sync: per-CTA release-flags + parallel acquire-polls (no
// atomics, no membar). Flags reset by gemm_pre_kernel each launch.
// ---------------------------------------------------------------------------
#define NTHR 256
// smem: sH[512][36] (h, k-major) + sW[512][20] (Wh cols) + sRed[256][20]
#define SMEM_FLOATS (512*36 + 512*20 + 256*20)

__device__ __forceinline__ float sigf(float x)     { return 1.f / (1.f + __expf(-x)); }
__device__ __forceinline__ float tanh_fast(float x){ return 2.f / (1.f + __expf(-2.f * x)) - 1.f; }

__global__ __launch_bounds__(NTHR, 1)
void lstm_kernel(const float* __restrict__ h0, const float* __restrict__ c0,
                 const float* __restrict__ ww, const float* __restrict__ mw,
                 float* __restrict__ out)
{
    extern __shared__ float smem[];
    float* sH   = smem;                 // sH[k*36 + b]
    float* sW   = smem + 512 * 36;      // sW[k*20 + j]
    float* sRed = sW + 512 * 20;        // sRed[tid*20 + v]

    const int tid = threadIdx.x;
    const int L0  = blockIdx.x * 4;

    // ---- load W_h slice once: col(j) = (j>>2)*512 + L0 + (j&3), rows 512+k ----
    for (int it = tid; it < 16 * 512; it += NTHR) {
        int k = it >> 4;
        int j = it & 15;
        int g = j >> 2, jl = j & 3;
        float w;
        if (g < 3) w = ww[(size_t)(512 + k) * GW + g * 512 + L0 + jl];
        else       w = mw[(size_t)(512 + k) * L_ + L0 + jl];
        sW[k * 20 + j] = w;
    }

    // dot-product mapping: 8-way K split (warp = K chunk), 4x4 register block
    const int s  = tid >> 5;            // K chunk 0..7 (k in [s*64, s*64+64))
    const int u  = tid & 31;
    const int b0 = (u >> 2) * 4;        // batch block
    const int j0 = (u & 3) * 4;         // column block
    const int kbase = s * 64;

    // epilogue mapping (tid < 128): one (b, l) pair per thread
    const int eb  = tid >> 2;
    const int ejl = tid & 3;
    float c_reg = 0.f;
    float pre_r[4];
    if (tid < 128) {
        c_reg = c0[eb * L_ + L0 + ejl];
        #pragma unroll
        for (int g = 0; g < 4; g++)
            pre_r[g] = g_pre[(size_t)eb * T_ * NG + g * 512 + L0 + ejl];
    }

    // initial sH from h0 [32][512]
    #pragma unroll
    for (int q = 0; q < 16; q++) {
        int fidx = q * 256 + tid;
        int b = fidx >> 7;
        int kf = fidx & 127;
        float4 v = *(const float4*)&h0[b * 512 + kf * 4];
        int kb = kf * 4;
        sH[(kb + 0) * 36 + b] = v.x;
        sH[(kb + 1) * 36 + b] = v.y;
        sH[(kb + 2) * 36 + b] = v.z;
        sH[(kb + 3) * 36 + b] = v.w;
    }

    float* hid  = out;
    float* cell = out + (size_t)B_ * T_ * L_;

    for (int t = 0; t < T_; t++) {
        __syncthreads();    // sH (and on t==0: sW) ready

        // ---- h-part dot product ----
        float acc[4][4];
        #pragma unroll
        for (int i = 0; i < 4; i++)
            #pragma unroll
            for (int j = 0; j < 4; j++) acc[i][j] = 0.f;

        const float* hp = sH + kbase * 36 + b0;
        const float* wp = sW + kbase * 20 + j0;
        #pragma unroll 8
        for (int kk = 0; kk < 64; kk++) {
            float4 hv = *(const float4*)hp;
            float4 wv = *(const float4*)wp;
            acc[0][0] += hv.x * wv.x; acc[0][1] += hv.x * wv.y;
            acc[0][2] += hv.x * wv.z; acc[0][3] += hv.x * wv.w;
            acc[1][0] += hv.y * wv.x; acc[1][1] += hv.y * wv.y;
            acc[1][2] += hv.y * wv.z; acc[1][3] += hv.y * wv.w;
            acc[2][0] += hv.z * wv.x; acc[2][1] += hv.z * wv.y;
            acc[2][2] += hv.z * wv.z; acc[2][3] += hv.z * wv.w;
            acc[3][0] += hv.w * wv.x; acc[3][1] += hv.w * wv.y;
            acc[3][2] += hv.w * wv.z; acc[3][3] += hv.w * wv.w;
            hp += 36; wp += 20;
        }
        #pragma unroll
        for (int i = 0; i < 4; i++) {
            float4 v = make_float4(acc[i][0], acc[i][1], acc[i][2], acc[i][3]);
            *(float4*)&sRed[tid * 20 + i * 4] = v;
        }
        __syncthreads();

        // ---- reduce K chunks + gate epilogue ----
        if (tid < 128) {
            float z[4];
            #pragma unroll
            for (int g = 0; g < 4; g++) {
                float v = 0.f;
                #pragma unroll
                for (int ss = 0; ss < 8; ss++)
                    v += sRed[(ss * 32 + (eb >> 2) * 4 + g) * 20 + (eb & 3) * 4 + ejl];
                z[g] = v + pre_r[g];
            }
            float ig = sigf(z[0]);
            float fg = sigf(z[1]);
            float og = sigf(z[2]);
            float mg = tanh_fast(z[3]);
            c_reg = fg * c_reg + ig * mg;
            float hn = og * tanh_fast(c_reg);
            size_t off = ((size_t)eb * T_ + t) * L_ + L0 + ejl;
            hid[off]  = hn;
            cell[off] = c_reg;
            if (t + 1 < T_) {   // prefetch next step's x-part early
                #pragma unroll
                for (int g = 0; g < 4; g++)
                    pre_r[g] = g_pre[((size_t)eb * T_ + (t + 1)) * NG + g * 512 + L0 + ejl];
            }
        }

        if (t + 1 < T_) {
            // ---- flag barrier: per-CTA release store, parallel acquire polls ----
            __syncthreads();                    // this CTA's h(t) stores done
            if (tid == 0)
                st_rel(&g_flags[blockIdx.x * 8], (unsigned)(t + 1));
            if (tid < NCTA) {
                const unsigned* fp = &g_flags[tid * 8];
                while (ld_acq(fp) < (unsigned)(t + 1)) { }
            }
            __syncthreads();                    // all 128 flags observed
            // ---- stage h(t) for next step ----
            #pragma unroll
            for (int q = 0; q < 16; q++) {
                int fidx = q * 256 + tid;
                int b = fidx >> 7;
                int kf = fidx & 127;
                float4 v = *(const float4*)&hid[((size_t)b * T_ + t) * L_ + kf * 4];
                int kb = kf * 4;
                sH[(kb + 0) * 36 + b] = v.x;
                sH[(kb + 1) * 36 + b] = v.y;
                sH[(kb + 2) * 36 + b] = v.z;
                sH[(kb + 3) * 36 + b] = v.w;
            }
        }
    }
}

// ---------------------------------------------------------------------------
extern "C" void kernel_launch(void* const* d_in, const int* in_sizes, int n_in,
                              void* d_out, int out_size)
{
    const float* x  = (const float*)d_in[0];
    const float* h0 = (const float*)d_in[1];
    const float* c0 = (const float*)d_in[2];
    const float* ww = (const float*)d_in[3];
    const float* wb = (const float*)d_in[4];
    const float* mw = (const float*)d_in[5];
    const float* mb = (const float*)d_in[6];
    float* out = (float*)d_out;

    cudaFuncSetAttribute(lstm_kernel,
                         cudaFuncAttributeMaxDynamicSharedMemorySize,
                         SMEM_FLOATS * (int)sizeof(float));

    gemm_pre_kernel<<<dim3(NG / 128, (B_ * T_) / 128), 256>>>(x, ww, wb, mw, mb);
    lstm_kernel<<<NCTA, NTHR, SMEM_FLOATS * (int)sizeof(float)>>>(h0, c0, ww, mw, out);
}

// round 7
// speedup vs baseline: 1.7838x; 1.5939x over previous
#include <cuda_runtime.h>
#include <cstdint>
#include <cstddef>

#define B_  32
#define T_  2048
#define D_  512
#define L_  512
#define NG  2048          // 3L gate cols + L candidate cols
#define GW  1536          // w_w column count

// 536 MB scratch for precomputed x-part of preactivations (+bias folded in).
// Layout: g_pre[(b*T + t)*NG + col]
__device__ float g_pre[(size_t)B_ * T_ * NG];

#define NCTA 128
// Per-CTA publication counters, 32B stride (one L2 sector each). No atomics.
__device__ unsigned int g_flags[NCTA * 8];
// Double-buffered h broadcast: g_hbuf[parity][l*32 + b]
__device__ float g_hbuf[2 * L_ * B_];

__device__ __forceinline__ unsigned ld_acq(const unsigned* p) {
    unsigned v;
    asm volatile("ld.acquire.gpu.global.u32 %0, [%1];" : "=r"(v) : "l"(p));
    return v;
}
__device__ __forceinline__ void st_rel(unsigned* p, unsigned v) {
    asm volatile("st.release.gpu.global.u32 [%0], %1;" :: "l"(p), "r"(v));
}

// ---------------------------------------------------------------------------
// Phase 1: PRE = X @ W_x + bias     (X: [65536, 512], W_x: [512, 2048])
// 128x128 tile, 8x8 microtile, 2 CTAs/SM. Also resets the step flags
// (stream-ordered before lstm_kernel).
// ---------------------------------------------------------------------------
__global__ __launch_bounds__(256, 2)
void gemm_pre_kernel(const float* __restrict__ X,
                     const float* __restrict__ ww, const float* __restrict__ wb,
                     const float* __restrict__ mw, const float* __restrict__ mb)
{
    __shared__ float As[16][132];   // A tile, transposed: As[k][m], m=0..127
    __shared__ float Bs[16][136];   // B tile: Bs[k][n], n=0..127

    const int tid = threadIdx.x;
    if (blockIdx.x == 0 && blockIdx.y == 0) {
        #pragma unroll
        for (int r = 0; r < 4; r++) g_flags[tid * 4 + r] = 0u;
    }

    const int n0 = blockIdx.x * 128;
    const int m0 = blockIdx.y * 128;
    const int tx = tid & 15;        // n direction (16 * 8 = 128)
    const int ty = tid >> 4;        // m direction (16 * 8 = 128)

    const float* Bp; int ldb; const float* bias;
    if (n0 < GW) { Bp = ww + n0;        ldb = GW; bias = wb + n0; }
    else         { Bp = mw + (n0 - GW); ldb = L_; bias = mb + (n0 - GW); }

    float acc[8][8];
    #pragma unroll
    for (int i = 0; i < 8; i++)
        #pragma unroll
        for (int j = 0; j < 8; j++) acc[i][j] = 0.f;

    const int arow = tid >> 1;          // 0..127
    const int ak   = (tid & 1) * 8;     // 0 or 8
    const int brow = tid >> 4;          // 0..15
    const int bc   = (tid & 15) * 8;    // 0..120

    for (int k0 = 0; k0 < D_; k0 += 16) {
        {
            float4 v0 = *(const float4*)&X[(size_t)(m0 + arow) * D_ + k0 + ak];
            float4 v1 = *(const float4*)&X[(size_t)(m0 + arow) * D_ + k0 + ak + 4];
            As[ak + 0][arow] = v0.x; As[ak + 1][arow] = v0.y;
            As[ak + 2][arow] = v0.z; As[ak + 3][arow] = v0.w;
            As[ak + 4][arow] = v1.x; As[ak + 5][arow] = v1.y;
            As[ak + 6][arow] = v1.z; As[ak + 7][arow] = v1.w;
        }
        {
            float4 v0 = *(const float4*)&Bp[(size_t)(k0 + brow) * ldb + bc];
            float4 v1 = *(const float4*)&Bp[(size_t)(k0 + brow) * ldb + bc + 4];
            *(float4*)&Bs[brow][bc]     = v0;
            *(float4*)&Bs[brow][bc + 4] = v1;
        }
        __syncthreads();

        #pragma unroll
        for (int kk = 0; kk < 16; kk++) {
            float a[8], b[8];
            *(float4*)(a)     = *(const float4*)&As[kk][ty * 8];
            *(float4*)(a + 4) = *(const float4*)&As[kk][ty * 8 + 4];
            *(float4*)(b)     = *(const float4*)&Bs[kk][tx * 8];
            *(float4*)(b + 4) = *(const float4*)&Bs[kk][tx * 8 + 4];
            #pragma unroll
            for (int i = 0; i < 8; i++)
                #pragma unroll
                for (int j = 0; j < 8; j++)
                    acc[i][j] += a[i] * b[j];
        }
        __syncthreads();
    }

    float bj[8];
    *(float4*)(bj)     = *(const float4*)&bias[tx * 8];
    *(float4*)(bj + 4) = *(const float4*)&bias[tx * 8 + 4];
    #pragma unroll
    for (int i = 0; i < 8; i++) {
        int r = m0 + ty * 8 + i;
        float4 o0, o1;
        o0.x = acc[i][0] + bj[0]; o0.y = acc[i][1] + bj[1];
        o0.z = acc[i][2] + bj[2]; o0.w = acc[i][3] + bj[3];
        o1.x = acc[i][4] + bj[4]; o1.y = acc[i][5] + bj[5];
        o1.z = acc[i][6] + bj[6]; o1.w = acc[i][7] + bj[7];
        *(float4*)&g_pre[(size_t)r * NG + n0 + tx * 8]     = o0;
        *(float4*)&g_pre[(size_t)r * NG + n0 + tx * 8 + 4] = o1;
    }
}

// ---------------------------------------------------------------------------
// Phase 2: persistent recurrent kernel, decentralized pipelined handoff.
// 128 CTAs, CTA i owns l in [4i, 4i+4) => 16 gate columns.
// h(t) published per-CTA to double-buffered g_hbuf + per-CTA flag (=t+1).
// Warp s (k-chunk [64s,64s+64)) polls only its 16 producer flags, copies its
// 8KB h block to smem, and computes — no grid barrier, no full staging sync.
// ---------------------------------------------------------------------------
#define NTHR 256
// smem: sH[512][36] (h, k-major) + sW[512][20] (Wh cols) + sRed[256][20]
#define SMEM_FLOATS (512*36 + 512*20 + 256*20)

__device__ __forceinline__ float sigf(float x)     { return 1.f / (1.f + __expf(-x)); }
__device__ __forceinline__ float tanh_fast(float x){ return 2.f / (1.f + __expf(-2.f * x)) - 1.f; }

__global__ __launch_bounds__(NTHR, 1)
void lstm_kernel(const float* __restrict__ h0, const float* __restrict__ c0,
                 const float* __restrict__ ww, const float* __restrict__ mw,
                 float* __restrict__ out)
{
    extern __shared__ float smem[];
    float* sH   = smem;                 // sH[k*36 + b]
    float* sW   = smem + 512 * 36;      // sW[k*20 + j]
    float* sRed = sW + 512 * 20;        // sRed[tid*20 + v]

    const int tid = threadIdx.x;
    const int L0  = blockIdx.x * 4;

    // ---- load W_h slice once: col(j) = (j>>2)*512 + L0 + (j&3), rows 512+k ----
    for (int it = tid; it < 16 * 512; it += NTHR) {
        int k = it >> 4;
        int j = it & 15;
        int g = j >> 2, jl = j & 3;
        float w;
        if (g < 3) w = ww[(size_t)(512 + k) * GW + g * 512 + L0 + jl];
        else       w = mw[(size_t)(512 + k) * L_ + L0 + jl];
        sW[k * 20 + j] = w;
    }

    // dot-product mapping: 8-way K split (warp = K chunk), 4x4 register block
    const int s  = tid >> 5;            // K chunk 0..7 (k in [s*64, s*64+64))
    const int u  = tid & 31;
    const int b0 = (u >> 2) * 4;        // batch block
    const int j0 = (u & 3) * 4;         // column block
    const int kbase = s * 64;

    // epilogue mapping (tid < 128): one (b, l) pair per thread
    const int eb  = tid >> 2;
    const int ejl = tid & 3;
    float c_reg = 0.f;
    float pre_r[4];
    if (tid < 128) {
        c_reg = c0[eb * L_ + L0 + ejl];
        #pragma unroll
        for (int g = 0; g < 4; g++)
            pre_r[g] = g_pre[(size_t)eb * T_ * NG + g * 512 + L0 + ejl];
    }

    // ---- publish this CTA's slice of h0 into buffer 0, flag = 1 ----
    if (tid < 128)
        g_hbuf[(L0 + ejl) * 32 + eb] = h0[eb * L_ + L0 + ejl];
    if (tid < 128) __threadfence();
    __syncthreads();            // h0 slice + sW ready
    if (tid == 0) st_rel(&g_flags[blockIdx.x * 8], 1u);

    float* hid  = out;
    float* cell = out + (size_t)B_ * T_ * L_;

    // poll target for this warp's 16 producers
    const unsigned* myflag = &g_flags[(s * 16 + (u & 15)) * 8];

    for (int t = 0; t < T_; t++) {
        const float* buf = g_hbuf + (size_t)(t & 1) * (L_ * 32);

        // ---- per-warp: wait for my 16 producers, copy my 8KB h block ----
        {
            const unsigned tgt = (unsigned)(t + 1);
            for (;;) {
                unsigned v = ld_acq(myflag);
                if (__all_sync(0xffffffffu, v >= tgt)) break;
            }
            #pragma unroll
            for (int q = 0; q < 16; q++) {
                int f = q * 32 + u;
                int krow = f >> 3;
                int c4 = (f & 7) * 4;
                float4 v4 = *(const float4*)&buf[(kbase + krow) * 32 + c4];
                *(float4*)&sH[(kbase + krow) * 36 + c4] = v4;
            }
        }

        // ---- h-part dot product (warp-local data; no CTA sync needed) ----
        float acc[4][4];
        #pragma unroll
        for (int i = 0; i < 4; i++)
            #pragma unroll
            for (int j = 0; j < 4; j++) acc[i][j] = 0.f;

        const float* hp = sH + kbase * 36 + b0;
        const float* wp = sW + kbase * 20 + j0;
        #pragma unroll 8
        for (int kk = 0; kk < 64; kk++) {
            float4 hv = *(const float4*)hp;
            float4 wv = *(const float4*)wp;
            acc[0][0] += hv.x * wv.x; acc[0][1] += hv.x * wv.y;
            acc[0][2] += hv.x * wv.z; acc[0][3] += hv.x * wv.w;
            acc[1][0] += hv.y * wv.x; acc[1][1] += hv.y * wv.y;
            acc[1][2] += hv.y * wv.z; acc[1][3] += hv.y * wv.w;
            acc[2][0] += hv.z * wv.x; acc[2][1] += hv.z * wv.y;
            acc[2][2] += hv.z * wv.z; acc[2][3] += hv.z * wv.w;
            acc[3][0] += hv.w * wv.x; acc[3][1] += hv.w * wv.y;
            acc[3][2] += hv.w * wv.z; acc[3][3] += hv.w * wv.w;
            hp += 36; wp += 20;
        }
        #pragma unroll
        for (int i = 0; i < 4; i++) {
            float4 v = make_float4(acc[i][0], acc[i][1], acc[i][2], acc[i][3]);
            *(float4*)&sRed[tid * 20 + i * 4] = v;
        }
        __syncthreads();    // all chunks' partials in sRed

        // ---- reduce K chunks + gate epilogue + publish h(t+1) ----
        if (tid < 128) {
            float z[4];
            #pragma unroll
            for (int g = 0; g < 4; g++) {
                float v = 0.f;
                #pragma unroll
                for (int ss = 0; ss < 8; ss++)
                    v += sRed[(ss * 32 + (eb >> 2) * 4 + g) * 20 + (eb & 3) * 4 + ejl];
                z[g] = v + pre_r[g];
            }
            float ig = sigf(z[0]);
            float fg = sigf(z[1]);
            float og = sigf(z[2]);
            float mg = tanh_fast(z[3]);
            c_reg = fg * c_reg + ig * mg;
            float hn = og * tanh_fast(c_reg);
            size_t off = ((size_t)eb * T_ + t) * L_ + L0 + ejl;
            hid[off]  = hn;
            cell[off] = c_reg;
            if (t + 1 < T_) {
                // publish h(t+1) to the other parity buffer
                float* nb = g_hbuf + (size_t)((t + 1) & 1) * (L_ * 32);
                nb[(L0 + ejl) * 32 + eb] = hn;
                __threadfence();
                // prefetch next step's x-part
                #pragma unroll
                for (int g = 0; g < 4; g++)
                    pre_r[g] = g_pre[((size_t)eb * T_ + (t + 1)) * NG + g * 512 + L0 + ejl];
            }
        }
        __syncthreads();    // sRed reads done (WAR) + h(t+1) stores fenced
        if (t + 1 < T_ && tid == 0)
            st_rel(&g_flags[blockIdx.x * 8], (unsigned)(t + 2));
    }
}

// ---------------------------------------------------------------------------
extern "C" void kernel_launch(void* const* d_in, const int* in_sizes, int n_in,
                              void* d_out, int out_size)
{
    const float* x  = (const float*)d_in[0];
    const float* h0 = (const float*)d_in[1];
    const float* c0 = (const float*)d_in[2];
    const float* ww = (const float*)d_in[3];
    const float* wb = (const float*)d_in[4];
    const float* mw = (const float*)d_in[5];
    const float* mb = (const float*)d_in[6];
    float* out = (float*)d_out;

    cudaFuncSetAttribute(lstm_kernel,
                         cudaFuncAttributeMaxDynamicSharedMemorySize,
                         SMEM_FLOATS * (int)sizeof(float));

    gemm_pre_kernel<<<dim3(NG / 128, (B_ * T_) / 128), 256>>>(x, ww, wb, mw, mb);
    lstm_kernel<<<NCTA, NTHR, SMEM_FLOATS * (int)sizeof(float)>>>(h0, c0, ww, mw, out);
}